// round 2
// baseline (speedup 1.0000x reference)
#include <cuda_runtime.h>

#define Nn 50000
#define E0 800000
#define ETOT 850000
#define HCc 256
#define CAP 2048

// ---------------- device scratch (static: no runtime allocation allowed) ----
__device__ float g_h[(size_t)Nn * HCc];          // per-layer h = x@W
__device__ float g_x[4][(size_t)Nn * HCc];       // x1..x4
__device__ float g_esed[(size_t)Nn * 8];         // es[4] | ed[4] per node
__device__ int   g_rowptr[Nn + 1];
__device__ int   g_cnt[Nn];
__device__ int   g_csrc[ETOT];

// ---------------- CSR build ------------------------------------------------
__global__ void zero_cnt_kernel() {
    int i = blockIdx.x * blockDim.x + threadIdx.x;
    if (i < Nn) g_cnt[i] = 0;
}

__global__ void count_kernel(const int* __restrict__ ei) {
    int i = blockIdx.x * blockDim.x + threadIdx.x;
    if (i >= ETOT) return;
    int dst = (i < E0) ? ei[E0 + i] : (i - E0);
    atomicAdd(&g_cnt[dst], 1);
}

__global__ void scan_kernel() {
    __shared__ int s[1024];
    int tid = threadIdx.x;
    if (tid == 0) g_rowptr[0] = 0;
    int carry = 0;
    for (int base = 0; base < Nn; base += 1024) {
        int v = (base + tid < Nn) ? g_cnt[base + tid] : 0;
        s[tid] = v;
        __syncthreads();
        for (int off = 1; off < 1024; off <<= 1) {
            int t = (tid >= off) ? s[tid - off] : 0;
            __syncthreads();
            s[tid] += t;
            __syncthreads();
        }
        if (base + tid < Nn) g_rowptr[base + tid + 1] = carry + s[tid];
        carry += s[1023];
        __syncthreads();
    }
}

__global__ void fill_kernel(const int* __restrict__ ei) {
    int i = blockIdx.x * blockDim.x + threadIdx.x;
    if (i >= ETOT) return;
    int src, dst;
    if (i < E0) { src = ei[i]; dst = ei[E0 + i]; }
    else        { src = i - E0; dst = i - E0; }
    int pos = g_rowptr[dst] + atomicAdd(&g_cnt[dst], 1);
    g_csrc[pos] = src;
}

// ---------------- GEMM: g_h = (A [+ A2]) @ W  (A:[N,K], W:[K,256]) ----------
// Classic 64x64 tile, BK=16, 256 threads, 4x4 per-thread micro-tile, fp32.
__global__ void gemm_kernel(const float* __restrict__ A,
                            const float* __restrict__ A2,
                            const float* __restrict__ W, int K) {
    __shared__ float As[16][64];
    __shared__ float Bs[16][64];
    int tid = threadIdx.x;
    int m0 = blockIdx.x * 64, n0 = blockIdx.y * 64;
    int tx = tid & 15, ty = tid >> 4;
    int arow = tid >> 2, aq = (tid & 3) * 4;
    int brow = tid >> 4, bc = (tid & 15) * 4;
    int gm = m0 + arow;
    float acc[4][4] = {};

    for (int k0 = 0; k0 < K; k0 += 16) {
        float4 av = make_float4(0.f, 0.f, 0.f, 0.f);
        if (gm < Nn) {
            av = *(const float4*)(A + (size_t)gm * K + k0 + aq);
            if (A2) {
                float4 a2 = *(const float4*)(A2 + (size_t)gm * K + k0 + aq);
                av.x += a2.x; av.y += a2.y; av.z += a2.z; av.w += a2.w;
            }
        }
        As[aq + 0][arow] = av.x;
        As[aq + 1][arow] = av.y;
        As[aq + 2][arow] = av.z;
        As[aq + 3][arow] = av.w;
        *(float4*)&Bs[brow][bc] =
            *(const float4*)(W + (size_t)(k0 + brow) * HCc + n0 + bc);
        __syncthreads();
#pragma unroll
        for (int k = 0; k < 16; k++) {
            float4 a = *(const float4*)&As[k][ty * 4];
            float4 b = *(const float4*)&Bs[k][tx * 4];
            acc[0][0] += a.x * b.x; acc[0][1] += a.x * b.y;
            acc[0][2] += a.x * b.z; acc[0][3] += a.x * b.w;
            acc[1][0] += a.y * b.x; acc[1][1] += a.y * b.y;
            acc[1][2] += a.y * b.z; acc[1][3] += a.y * b.w;
            acc[2][0] += a.z * b.x; acc[2][1] += a.z * b.y;
            acc[2][2] += a.z * b.z; acc[2][3] += a.z * b.w;
            acc[3][0] += a.w * b.x; acc[3][1] += a.w * b.y;
            acc[3][2] += a.w * b.z; acc[3][3] += a.w * b.w;
        }
        __syncthreads();
    }
#pragma unroll
    for (int i = 0; i < 4; i++) {
        int gr = m0 + ty * 4 + i;
        if (gr < Nn) {
            float4 o = make_float4(acc[i][0], acc[i][1], acc[i][2], acc[i][3]);
            *(float4*)(g_h + (size_t)gr * HCc + n0 + tx * 4) = o;
        }
    }
}

// ---------------- es/ed logits: one block per node --------------------------
__global__ void esed_kernel(const float* __restrict__ asrc,
                            const float* __restrict__ adst) {
    int n = blockIdx.x, tid = threadIdx.x, l = tid & 63;
    float hv = g_h[(size_t)n * HCc + tid];
    __shared__ float s1[256], s2[256];
    s1[tid] = hv * asrc[tid];
    s2[tid] = hv * adst[tid];
    __syncthreads();
    for (int off = 32; off >= 1; off >>= 1) {
        if (l < off) { s1[tid] += s1[tid + off]; s2[tid] += s2[tid + off]; }
        __syncthreads();
    }
    if (l == 0) {
        int head = tid >> 6;
        g_esed[(size_t)n * 8 + head]     = s1[tid];
        g_esed[(size_t)n * 8 + 4 + head] = s2[tid];
    }
}

// ---------------- per-node edge softmax + weighted aggregation --------------
__device__ __forceinline__ float sel4(float4 v, int h) {
    return h == 0 ? v.x : h == 1 ? v.y : h == 2 ? v.z : v.w;
}
__device__ __forceinline__ float lrelu(float v) {
    return v > 0.f ? v : 0.2f * v;
}

__global__ void agg_kernel(const float* __restrict__ bias,
                           float* __restrict__ Out, int do_relu) {
    __shared__ float e_s[4 * CAP];
    __shared__ int   src_s[CAP];
    __shared__ float red[256];
    __shared__ float m_s[4], inv_s[4];

    int n = blockIdx.x, tid = threadIdx.x;
    int head = tid >> 6, l = tid & 63;
    int beg = g_rowptr[n];
    int deg = g_rowptr[n + 1] - beg;
    float4 ed4 = *(const float4*)(g_esed + (size_t)n * 8 + 4);

    // compute edge logits for this dst, cache in smem
    int total = deg * 4;
    for (int i = tid; i < total; i += 256) {
        int eidx = i >> 2, hh = i & 3;
        int s = g_csrc[beg + eidx];
        float ev = lrelu(g_esed[(size_t)s * 8 + hh] + sel4(ed4, hh));
        if (eidx < CAP) {
            e_s[hh * CAP + eidx] = ev;
            if (hh == 0) src_s[eidx] = s;
        }
    }
    __syncthreads();

    int dc = min(deg, CAP);
    // per-head max
    float mx = -1e30f;
    for (int i = l; i < dc; i += 64) mx = fmaxf(mx, e_s[head * CAP + i]);
    if (deg > CAP) {
        float edh = sel4(ed4, head);
        for (int i = CAP + l; i < deg; i += 64) {
            int s = g_csrc[beg + i];
            mx = fmaxf(mx, lrelu(g_esed[(size_t)s * 8 + head] + edh));
        }
    }
    red[tid] = mx;
    __syncthreads();
    for (int off = 32; off >= 1; off >>= 1) {
        if (l < off) red[tid] = fmaxf(red[tid], red[tid + off]);
        __syncthreads();
    }
    if (l == 0) m_s[head] = red[tid];
    __syncthreads();
    float m = m_s[head];

    // sum exp (convert e_s -> ex in place)
    float sum = 0.f;
    for (int i = l; i < dc; i += 64) {
        float ex = __expf(e_s[head * CAP + i] - m);
        e_s[head * CAP + i] = ex;
        sum += ex;
    }
    if (deg > CAP) {
        float edh = sel4(ed4, head);
        for (int i = CAP + l; i < deg; i += 64) {
            int s = g_csrc[beg + i];
            sum += __expf(lrelu(g_esed[(size_t)s * 8 + head] + edh) - m);
        }
    }
    red[tid] = sum;
    __syncthreads();
    for (int off = 32; off >= 1; off >>= 1) {
        if (l < off) red[tid] += red[tid + off];
        __syncthreads();
    }
    if (l == 0) inv_s[head] = 1.f / (red[tid] + 1e-16f);
    __syncthreads();
    float inv = inv_s[head];

    // weighted accumulation: thread owns output channel tid = head*64 + c
    float acc = 0.f;
#pragma unroll 4
    for (int i = 0; i < dc; ++i) {
        acc += e_s[head * CAP + i] * g_h[(size_t)src_s[i] * HCc + tid];
    }
    if (deg > CAP) {
        float edh = sel4(ed4, head);
        for (int i = CAP; i < deg; ++i) {
            int s = g_csrc[beg + i];
            float ex = __expf(lrelu(g_esed[(size_t)s * 8 + head] + edh) - m);
            acc += ex * g_h[(size_t)s * HCc + tid];
        }
    }
    float o = acc * inv + bias[tid];
    if (do_relu) o = fmaxf(o, 0.f);
    Out[(size_t)n * HCc + tid] = o;
}

// ---------------- launch ----------------------------------------------------
extern "C" void kernel_launch(void* const* d_in, const int* in_sizes, int n_in,
                              void* d_out, int out_size) {
    const float* x  = (const float*)d_in[0];
    const int*   ei = (const int*)d_in[1];
    const float *W[4], *Asr[4], *Adt[4], *B[4];
    for (int lyr = 0; lyr < 4; lyr++) {
        W[lyr]   = (const float*)d_in[2 + 4 * lyr];
        Asr[lyr] = (const float*)d_in[3 + 4 * lyr];
        Adt[lyr] = (const float*)d_in[4 + 4 * lyr];
        B[lyr]   = (const float*)d_in[5 + 4 * lyr];
    }
    float* out = (float*)d_out;

    float* pxbase = nullptr;
    cudaGetSymbolAddress((void**)&pxbase, g_x);
    float* px[4];
    for (int i = 0; i < 4; i++) px[i] = pxbase + (size_t)i * Nn * HCc;

    // CSR build (per launch; deterministic up to fp-neutral edge ordering)
    zero_cnt_kernel<<<(Nn + 255) / 256, 256>>>();
    count_kernel<<<(ETOT + 255) / 256, 256>>>(ei);
    scan_kernel<<<1, 1024>>>();
    zero_cnt_kernel<<<(Nn + 255) / 256, 256>>>();
    fill_kernel<<<(ETOT + 255) / 256, 256>>>(ei);

    dim3 gg((Nn + 63) / 64, HCc / 64);

    // L1: x -> x1
    gemm_kernel<<<gg, 256>>>(x, nullptr, W[0], 128);
    esed_kernel<<<Nn, 256>>>(Asr[0], Adt[0]);
    agg_kernel<<<Nn, 256>>>(B[0], px[0], 1);
    // L2: x1 -> x2
    gemm_kernel<<<gg, 256>>>(px[0], nullptr, W[1], HCc);
    esed_kernel<<<Nn, 256>>>(Asr[1], Adt[1]);
    agg_kernel<<<Nn, 256>>>(B[1], px[1], 1);
    // L3: x2+x1 -> x3
    gemm_kernel<<<gg, 256>>>(px[1], px[0], W[2], HCc);
    esed_kernel<<<Nn, 256>>>(Asr[2], Adt[2]);
    agg_kernel<<<Nn, 256>>>(B[2], px[2], 1);
    // L4: x2+x3 -> x4
    gemm_kernel<<<gg, 256>>>(px[1], px[2], W[3], HCc);
    esed_kernel<<<Nn, 256>>>(Asr[3], Adt[3]);
    agg_kernel<<<Nn, 256>>>(B[3], px[3], 1);
    // L5 (reuses layer-4 params, no relu): x4+x3 -> out
    gemm_kernel<<<gg, 256>>>(px[3], px[2], W[3], HCc);
    esed_kernel<<<Nn, 256>>>(Asr[3], Adt[3]);
    agg_kernel<<<Nn, 256>>>(B[3], out, 0);
}